// round 10
// baseline (speedup 1.0000x reference)
#include <cuda_runtime.h>
#include <math.h>

// ---------------- problem constants ----------------
#define S_TOT   20197
#define BATCH   2
#define T_TOT   40394          // BATCH * S_TOT
#define DMODEL  256
#define NHEAD   8
#define HDIM    32
#define NLEV    4
#define NPNT    4
#define DFF     1024
#define NLAYERS 6

// level geometry
__device__ __forceinline__ void level_consts(int l, int& H, int& W, int& start) {
    const int Hs[4] = {100, 50, 25, 13};
    const int Ws[4] = {152, 76, 38, 19};
    const int St[4] = {0, 15200, 19000, 19950};
    H = Hs[l]; W = Ws[l]; start = St[l];
}

// ---------------- scratch (static device memory, no allocs) ----------------
__device__ float g_value[(size_t)T_TOT * DMODEL];
__device__ float g_q    [(size_t)T_TOT * DMODEL];
__device__ float g_off  [(size_t)T_TOT * DMODEL];
__device__ float g_attn [(size_t)T_TOT * (NHEAD * NLEV * NPNT)];
__device__ float g_acc  [(size_t)T_TOT * DMODEL];
__device__ float g_a    [(size_t)T_TOT * DMODEL];
__device__ float g_ff   [(size_t)T_TOT * DFF];
__device__ float g_cur  [(size_t)T_TOT * DMODEL];
__device__ float g_ref  [(size_t)T_TOT * NLEV * 2];

// ---------------- SGEMM: C[M,N] = A[M,K] @ W[K,N] + bias (opt relu) ---------
// BM=BN=128, BK=16, 256 threads, 8x8 microtile per thread.
__global__ __launch_bounds__(256) void sgemm_bias(
    const float* __restrict__ A, const float* __restrict__ W,
    const float* __restrict__ bias, float* __restrict__ C,
    int M, int N, int K, int relu)
{
    __shared__ float As[16][132];   // transposed A tile, padded
    __shared__ float Bs[16][128];

    const int tid  = threadIdx.x;
    const int bm   = blockIdx.y, bn = blockIdx.x;
    const int trow = tid >> 4;      // 0..15
    const int tcol = tid & 15;      // 0..15
    const int rowBase = bm * 128;

    // global-load indexing
    const int aRow0 = tid >> 2;          // 0..63 (+64)
    const int aCol  = (tid & 3) * 4;     // 0,4,8,12
    const int bRow0 = tid >> 5;          // 0..7 (+8)
    const int bCol  = (tid & 31) * 4;    // 0..124

    float acc[8][8];
    #pragma unroll
    for (int i = 0; i < 8; i++)
        #pragma unroll
        for (int j = 0; j < 8; j++) acc[i][j] = 0.f;

    for (int k0 = 0; k0 < K; k0 += 16) {
        #pragma unroll
        for (int i = 0; i < 2; i++) {
            int ar = aRow0 + i * 64;
            int gr = rowBase + ar;
            float4 v = make_float4(0.f, 0.f, 0.f, 0.f);
            if (gr < M) v = *(const float4*)(A + (size_t)gr * K + k0 + aCol);
            As[aCol + 0][ar] = v.x; As[aCol + 1][ar] = v.y;
            As[aCol + 2][ar] = v.z; As[aCol + 3][ar] = v.w;
        }
        #pragma unroll
        for (int i = 0; i < 2; i++) {
            int br = bRow0 + i * 8;
            float4 v = *(const float4*)(W + (size_t)(k0 + br) * N + bn * 128 + bCol);
            *(float4*)(&Bs[br][bCol]) = v;
        }
        __syncthreads();

        #pragma unroll
        for (int kk = 0; kk < 16; kk++) {
            float a[8], b[8];
            *(float4*)(a)     = *(const float4*)(&As[kk][trow * 8]);
            *(float4*)(a + 4) = *(const float4*)(&As[kk][trow * 8 + 4]);
            *(float4*)(b)     = *(const float4*)(&Bs[kk][tcol * 8]);
            *(float4*)(b + 4) = *(const float4*)(&Bs[kk][tcol * 8 + 4]);
            #pragma unroll
            for (int i = 0; i < 8; i++)
                #pragma unroll
                for (int j = 0; j < 8; j++)
                    acc[i][j] = fmaf(a[i], b[j], acc[i][j]);
        }
        __syncthreads();
    }

    float bv[8];
    *(float4*)(bv)     = *(const float4*)(bias + bn * 128 + tcol * 8);
    *(float4*)(bv + 4) = *(const float4*)(bias + bn * 128 + tcol * 8 + 4);

    #pragma unroll
    for (int i = 0; i < 8; i++) {
        int gr = rowBase + trow * 8 + i;
        if (gr < M) {
            float o[8];
            #pragma unroll
            for (int j = 0; j < 8; j++) {
                o[j] = acc[i][j] + bv[j];
                if (relu) o[j] = fmaxf(o[j], 0.f);
            }
            float* cp = C + (size_t)gr * N + bn * 128 + tcol * 8;
            *(float4*)(cp)     = *(float4*)(o);
            *(float4*)(cp + 4) = *(float4*)(o + 4);
        }
    }
}

// ---------------- elementwise add: q = cur + pos ----------------
__global__ void ew_add(const float* __restrict__ x, const float* __restrict__ y,
                       float* __restrict__ out, int n)
{
    int i = blockIdx.x * blockDim.x + threadIdx.x;
    if (i < n) out[i] = x[i] + y[i];
}

// ---------------- reference points ----------------
__global__ void compute_ref(const float* __restrict__ vr, float* __restrict__ ref)
{
    int t = blockIdx.x * blockDim.x + threadIdx.x;
    if (t >= T_TOT) return;
    int b = t / S_TOT;
    int s = t - b * S_TOT;

    int lq, rem;
    if      (s >= 19950) { lq = 3; rem = s - 19950; }
    else if (s >= 19000) { lq = 2; rem = s - 19000; }
    else if (s >= 15200) { lq = 1; rem = s - 15200; }
    else                 { lq = 0; rem = s; }

    int H, W, st;
    level_consts(lq, H, W, st);
    int iy = rem / W;
    int ix = rem - iy * W;

    const float* v = vr + b * (NLEV * 2);
    float rx = (ix + 0.5f) / (v[lq * 2 + 0] * (float)W);
    float ry = (iy + 0.5f) / (v[lq * 2 + 1] * (float)H);

    #pragma unroll
    for (int l = 0; l < 4; l++) {
        ref[(size_t)t * 8 + l * 2 + 0] = rx * v[l * 2 + 0];
        ref[(size_t)t * 8 + l * 2 + 1] = ry * v[l * 2 + 1];
    }
}

// ---------------- softmax over 16 (per token,head) ----------------
__global__ void softmax16(float* __restrict__ attn, int n)
{
    int i = blockIdx.x * blockDim.x + threadIdx.x;
    if (i >= n) return;
    float* p = attn + (size_t)i * 16;
    float v[16], m = -1e30f;
    #pragma unroll
    for (int j = 0; j < 16; j++) { v[j] = p[j]; m = fmaxf(m, v[j]); }
    float s = 0.f;
    #pragma unroll
    for (int j = 0; j < 16; j++) { v[j] = expf(v[j] - m); s += v[j]; }
    float inv = 1.f / s;
    #pragma unroll
    for (int j = 0; j < 16; j++) p[j] = v[j] * inv;
}

// ---------------- MSDA bilinear sampling ----------------
// one block per token (256 thr = 8 warps = 8 heads; lane = head-dim)
__global__ __launch_bounds__(256) void msda_sample(
    const float* __restrict__ value, const float* __restrict__ off,
    const float* __restrict__ attn, const float* __restrict__ ref,
    float* __restrict__ acc)
{
    const int t = blockIdx.x;
    const int h = threadIdx.x >> 5;
    const int d = threadIdx.x & 31;
    const int b = (t >= S_TOT) ? 1 : 0;

    const float* vb = value + (size_t)b * S_TOT * DMODEL;
    const float* rp = ref  + (size_t)t * 8;
    const float* op = off  + (size_t)t * DMODEL + h * 32;  // (h,l,p,2) -> h*32+l*8+p*2
    const float* ap = attn + (size_t)t * 128 + h * 16;
    const int hd = h * HDIM + d;

    float a = 0.f;
    #pragma unroll
    for (int l = 0; l < 4; l++) {
        int Hl, Wl, st;
        level_consts(l, Hl, Wl, st);
        const float* vlev = vb + (size_t)st * DMODEL;
        float rx = rp[l * 2], ry = rp[l * 2 + 1];
        float invW = 1.f / (float)Wl, invH = 1.f / (float)Hl;
        #pragma unroll
        for (int p = 0; p < 4; p++) {
            float ox = op[l * 8 + p * 2], oy = op[l * 8 + p * 2 + 1];
            float w  = ap[l * 4 + p];
            float lx = rx + ox * invW;
            float ly = ry + oy * invH;
            float px = lx * (float)Wl - 0.5f;
            float py = ly * (float)Hl - 0.5f;
            float fx = floorf(px), fy = floorf(py);
            float dx = px - fx, dy = py - fy;
            int x0 = (int)fx, y0 = (int)fy;
            int x1 = x0 + 1, y1 = y0 + 1;
            bool vx0 = (x0 >= 0) & (x0 < Wl), vx1 = (x1 >= 0) & (x1 < Wl);
            bool vy0 = (y0 >= 0) & (y0 < Hl), vy1 = (y1 >= 0) & (y1 < Hl);
            int cx0 = min(max(x0, 0), Wl - 1), cx1 = min(max(x1, 0), Wl - 1);
            int cy0 = min(max(y0, 0), Hl - 1), cy1 = min(max(y1, 0), Hl - 1);
            float w00 = (vx0 && vy0) ? (1.f - dx) * (1.f - dy) : 0.f;
            float w10 = (vx1 && vy0) ? dx * (1.f - dy) : 0.f;
            float w01 = (vx0 && vy1) ? (1.f - dx) * dy : 0.f;
            float w11 = (vx1 && vy1) ? dx * dy : 0.f;
            float v00 = vlev[(size_t)(cy0 * Wl + cx0) * DMODEL + hd];
            float v10 = vlev[(size_t)(cy0 * Wl + cx1) * DMODEL + hd];
            float v01 = vlev[(size_t)(cy1 * Wl + cx0) * DMODEL + hd];
            float v11 = vlev[(size_t)(cy1 * Wl + cx1) * DMODEL + hd];
            float s = v00 * w00 + v10 * w10 + v01 * w01 + v11 * w11;
            a = fmaf(w, s, a);
        }
    }
    acc[(size_t)t * DMODEL + hd] = a;
}

// ---------------- residual add + layernorm (row = 256) ----------------
__global__ __launch_bounds__(256) void add_ln(
    const float* __restrict__ x, const float* __restrict__ r,
    const float* __restrict__ g, const float* __restrict__ bta,
    float* __restrict__ out)
{
    __shared__ float warpsum[8];
    __shared__ float bcast;
    const int row = blockIdx.x, tid = threadIdx.x;
    const int lane = tid & 31, wid = tid >> 5;

    float v = x[(size_t)row * 256 + tid] + r[(size_t)row * 256 + tid];

    float s = v;
    #pragma unroll
    for (int o = 16; o > 0; o >>= 1) s += __shfl_xor_sync(0xFFFFFFFFu, s, o);
    if (lane == 0) warpsum[wid] = s;
    __syncthreads();
    if (tid == 0) {
        float tt = 0.f;
        #pragma unroll
        for (int i = 0; i < 8; i++) tt += warpsum[i];
        bcast = tt * (1.f / 256.f);
    }
    __syncthreads();
    float mean = bcast;
    float dcen = v - mean;

    float s2 = dcen * dcen;
    #pragma unroll
    for (int o = 16; o > 0; o >>= 1) s2 += __shfl_xor_sync(0xFFFFFFFFu, s2, o);
    if (lane == 0) warpsum[wid] = s2;
    __syncthreads();
    if (tid == 0) {
        float tt = 0.f;
        #pragma unroll
        for (int i = 0; i < 8; i++) tt += warpsum[i];
        bcast = tt * (1.f / 256.f);
    }
    __syncthreads();
    float var = bcast;

    out[(size_t)row * 256 + tid] = dcen * rsqrtf(var + 1e-5f) * g[tid] + bta[tid];
}

// ---------------- host orchestration ----------------
static inline void run_gemm(const float* A, const float* W, const float* bias,
                            float* C, int M, int N, int K, int relu)
{
    dim3 grid(N / 128, (M + 127) / 128);
    sgemm_bias<<<grid, 256>>>(A, W, bias, C, M, N, K, relu);
}

extern "C" void kernel_launch(void* const* d_in, const int* in_sizes, int n_in,
                              void* d_out, int out_size)
{
    const float* src     = (const float*)d_in[0];
    const float* pos     = (const float*)d_in[1];
    const float* vratios = (const float*)d_in[2];
    const float* W_value = (const float*)d_in[3];
    const float* b_value = (const float*)d_in[4];
    const float* W_off   = (const float*)d_in[5];
    const float* b_off   = (const float*)d_in[6];
    const float* W_attn  = (const float*)d_in[7];
    const float* b_attn  = (const float*)d_in[8];
    const float* W_out   = (const float*)d_in[9];
    const float* b_out   = (const float*)d_in[10];
    const float* ln1g    = (const float*)d_in[11];
    const float* ln1b    = (const float*)d_in[12];
    const float* W_ff1   = (const float*)d_in[13];
    const float* b_ff1   = (const float*)d_in[14];
    const float* W_ff2   = (const float*)d_in[15];
    const float* b_ff2   = (const float*)d_in[16];
    const float* ln2g    = (const float*)d_in[17];
    const float* ln2b    = (const float*)d_in[18];

    float *pval, *pq, *poff, *pattn, *pacc, *pa, *pff, *pcur, *pref;
    cudaGetSymbolAddress((void**)&pval,  g_value);
    cudaGetSymbolAddress((void**)&pq,    g_q);
    cudaGetSymbolAddress((void**)&poff,  g_off);
    cudaGetSymbolAddress((void**)&pattn, g_attn);
    cudaGetSymbolAddress((void**)&pacc,  g_acc);
    cudaGetSymbolAddress((void**)&pa,    g_a);
    cudaGetSymbolAddress((void**)&pff,   g_ff);
    cudaGetSymbolAddress((void**)&pcur,  g_cur);
    cudaGetSymbolAddress((void**)&pref,  g_ref);

    const int nElem = T_TOT * DMODEL;           // 10,340,864
    const int M = T_TOT;

    // reference points (valid_ratios constant across layers)
    compute_ref<<<(T_TOT + 255) / 256, 256>>>(vratios, pref);

    const float* cur = src;
    for (int i = 0; i < NLAYERS; i++) {
        const float* Wv  = W_value + (size_t)i * DMODEL * DMODEL;
        const float* bv  = b_value + (size_t)i * DMODEL;
        const float* Wof = W_off   + (size_t)i * DMODEL * DMODEL;
        const float* bof = b_off   + (size_t)i * DMODEL;
        const float* Wat = W_attn  + (size_t)i * DMODEL * 128;
        const float* bat = b_attn  + (size_t)i * 128;
        const float* Wo  = W_out   + (size_t)i * DMODEL * DMODEL;
        const float* bo  = b_out   + (size_t)i * DMODEL;
        const float* Wf1 = W_ff1   + (size_t)i * DMODEL * DFF;
        const float* bf1 = b_ff1   + (size_t)i * DFF;
        const float* Wf2 = W_ff2   + (size_t)i * DFF * DMODEL;
        const float* bf2 = b_ff2   + (size_t)i * DMODEL;

        // value projection
        run_gemm(cur, Wv, bv, pval, M, DMODEL, DMODEL, 0);
        // q = cur + pos
        ew_add<<<(nElem + 255) / 256, 256>>>(cur, pos, pq, nElem);
        // offsets / attention logits
        run_gemm(pq, Wof, bof, poff, M, DMODEL, DMODEL, 0);
        run_gemm(pq, Wat, bat, pattn, M, 128, DMODEL, 0);
        softmax16<<<(T_TOT * NHEAD + 255) / 256, 256>>>(pattn, T_TOT * NHEAD);
        // deformable sampling
        msda_sample<<<T_TOT, 256>>>(pval, poff, pattn, pref, pacc);
        // output projection + residual LN
        run_gemm(pacc, Wo, bo, pa, M, DMODEL, DMODEL, 0);
        add_ln<<<T_TOT, 256>>>(cur, pa, ln1g + (size_t)i * DMODEL,
                               ln1b + (size_t)i * DMODEL, pcur);
        // FFN
        run_gemm(pcur, Wf1, bf1, pff, M, DFF, DMODEL, 1);
        run_gemm(pff, Wf2, bf2, pa, M, DMODEL, DFF, 0);
        float* dst = (i == NLAYERS - 1) ? (float*)d_out : pcur;
        add_ln<<<T_TOT, 256>>>(pcur, pa, ln2g + (size_t)i * DMODEL,
                               ln2b + (size_t)i * DMODEL, dst);
        cur = pcur;
    }
}

// round 13
// speedup vs baseline: 1.4754x; 1.4754x over previous
#include <cuda_runtime.h>
#include <math.h>
#include <stdint.h>

// ---------------- problem constants ----------------
#define S_TOT   20197
#define BATCH   2
#define T_TOT   40394          // BATCH * S_TOT
#define DMODEL  256
#define NHEAD   8
#define HDIM    32
#define NLEV    4
#define NPNT    4
#define DFF     1024
#define NLAYERS 6

// level geometry
__device__ __forceinline__ void level_consts(int l, int& H, int& W, int& start) {
    const int Hs[4] = {100, 50, 25, 13};
    const int Ws[4] = {152, 76, 38, 19};
    const int St[4] = {0, 15200, 19000, 19950};
    H = Hs[l]; W = Ws[l]; start = St[l];
}

// ---------------- scratch (static device memory, no allocs) ----------------
__device__ float g_value[(size_t)T_TOT * DMODEL];
__device__ float g_q    [(size_t)T_TOT * DMODEL];
__device__ float g_off  [(size_t)T_TOT * DMODEL];
__device__ float g_attn [(size_t)T_TOT * (NHEAD * NLEV * NPNT)];
__device__ float g_acc  [(size_t)T_TOT * DMODEL];
__device__ float g_a    [(size_t)T_TOT * DMODEL];
__device__ float g_ff   [(size_t)T_TOT * DFF];
__device__ float g_cur  [(size_t)T_TOT * DMODEL];
__device__ float g_ref  [(size_t)T_TOT * NLEV * 2];

// ================= tf32 helpers ==========================
__device__ __forceinline__ uint32_t f2tf32(float f) {
    uint32_t r;
    asm("cvt.rna.tf32.f32 %0, %1;" : "=r"(r) : "f"(f));
    return r;
}

__device__ __forceinline__ void mma_16n8k8(float4& d,
    uint32_t a0, uint32_t a1, uint32_t a2, uint32_t a3,
    uint32_t b0, uint32_t b1)
{
    asm volatile(
        "mma.sync.aligned.m16n8k8.row.col.f32.tf32.tf32.f32 "
        "{%0,%1,%2,%3}, {%4,%5,%6,%7}, {%8,%9}, {%0,%1,%2,%3};"
        : "+f"(d.x), "+f"(d.y), "+f"(d.z), "+f"(d.w)
        : "r"(a0), "r"(a1), "r"(a2), "r"(a3), "r"(b0), "r"(b1));
}

// ================= mma.sync tf32 GEMM ======================================
// C[M,N] = A[M,K] @ W[K,N] + bias (optional relu).
// BM=BN=128, BK=16, 256 threads = 8 warps (2 x 4), warp tile 64x32.
//
// SMEM layout (A and B identical): [outer 128][16 floats], where the 16
// k-values of a row are permuted (col' = (k%4)*4 + k/4) and the 16B chunk
// index is XOR-swizzled with (row & 3). One uint4 LDS per fragment-pair,
// conflict-free.
__global__ __launch_bounds__(256) void gemm_tf32(
    const float* __restrict__ A, const float* __restrict__ W,
    const float* __restrict__ bias, float* __restrict__ C,
    int M, int N, int K, int relu)
{
    __shared__ uint32_t As[2][128 * 16];
    __shared__ uint32_t Bs[2][128 * 16];

    const int tid  = threadIdx.x;
    const int lane = tid & 31;
    const int wid  = tid >> 5;
    const int warpM = wid & 1;          // 0..1 -> M offset 0/64
    const int warpN = wid >> 1;         // 0..3 -> N offset 0/32/64/96
    const int m0 = blockIdx.y * 128;
    const int n0 = blockIdx.x * 128;

    const int qr = lane >> 2;           // 0..7
    const int qc = lane & 3;            // 0..3

    float4 acc[4][4];
    #pragma unroll
    for (int i = 0; i < 4; i++)
        #pragma unroll
        for (int j = 0; j < 4; j++)
            acc[i][j] = make_float4(0.f, 0.f, 0.f, 0.f);

    // loader role: warps 0-3 load A rows, warps 4-7 load B columns
    const bool isA = (tid < 128);
    const int  lrow = isA ? tid : (tid - 128);
    const int  swz  = lrow & 3;

    uint32_t stage[16];
    const int nChunks = K >> 4;

    // ---- global load of one BK chunk into registers ----
    auto g_load = [&](int k0) {
        if (isA) {
            int gr = m0 + lrow;
            if (gr < M) {
                const float4* p = (const float4*)(A + (size_t)gr * K + k0);
                #pragma unroll
                for (int j = 0; j < 4; j++) {
                    float4 v = p[j];
                    stage[4 * j + 0] = f2tf32(v.x);
                    stage[4 * j + 1] = f2tf32(v.y);
                    stage[4 * j + 2] = f2tf32(v.z);
                    stage[4 * j + 3] = f2tf32(v.w);
                }
            } else {
                #pragma unroll
                for (int j = 0; j < 16; j++) stage[j] = 0u;
            }
        } else {
            const float* p = W + (size_t)k0 * N + n0 + lrow;
            #pragma unroll
            for (int k = 0; k < 16; k++)
                stage[k] = f2tf32(p[(size_t)k * N]);
        }
    };

    // ---- store staged registers to smem buffer (permuted + swizzled) ----
    auto s_store = [&](int buf) {
        uint32_t* dst = isA ? &As[buf][0] : &Bs[buf][0];
        #pragma unroll
        for (int c = 0; c < 4; c++) {
            int pos = c ^ swz;
            uint4 v = make_uint4(stage[c], stage[c + 4], stage[c + 8], stage[c + 12]);
            *(uint4*)(dst + lrow * 16 + pos * 4) = v;
        }
    };

    // prologue
    g_load(0);
    s_store(0);
    __syncthreads();

    const int fpos = qc ^ (qr & 3);     // fragment chunk position

    for (int c = 0; c < nChunks; c++) {
        const int buf = c & 1;
        if (c + 1 < nChunks) g_load((c + 1) << 4);

        // ---- fragment loads ----
        uint4 afl[4], afh[4], bf[4];
        #pragma unroll
        for (int mt = 0; mt < 4; mt++) {
            int r = warpM * 64 + mt * 16 + qr;
            afl[mt] = *(const uint4*)(&As[buf][r * 16 + fpos * 4]);
            afh[mt] = *(const uint4*)(&As[buf][(r + 8) * 16 + fpos * 4]);
        }
        #pragma unroll
        for (int nt = 0; nt < 4; nt++) {
            int n = warpN * 32 + nt * 8 + qr;
            bf[nt] = *(const uint4*)(&Bs[buf][n * 16 + fpos * 4]);
        }

        // ---- 2 k-steps x 16 mmas ----
        #pragma unroll
        for (int mt = 0; mt < 4; mt++)
            #pragma unroll
            for (int nt = 0; nt < 4; nt++)
                mma_16n8k8(acc[mt][nt],
                           afl[mt].x, afh[mt].x, afl[mt].y, afh[mt].y,
                           bf[nt].x, bf[nt].y);
        #pragma unroll
        for (int mt = 0; mt < 4; mt++)
            #pragma unroll
            for (int nt = 0; nt < 4; nt++)
                mma_16n8k8(acc[mt][nt],
                           afl[mt].z, afh[mt].z, afl[mt].w, afh[mt].w,
                           bf[nt].z, bf[nt].w);

        __syncthreads();
        if (c + 1 < nChunks) {
            s_store((c + 1) & 1);
            __syncthreads();
        }
    }

    // ---- epilogue: bias + optional relu ----
    #pragma unroll
    for (int nt = 0; nt < 4; nt++) {
        int col = n0 + warpN * 32 + nt * 8 + qc * 2;
        float b0 = bias[col], b1 = bias[col + 1];
        #pragma unroll
        for (int mt = 0; mt < 4; mt++) {
            int row = m0 + warpM * 64 + mt * 16 + qr;
            float4 a = acc[mt][nt];
            float2 lo = make_float2(a.x + b0, a.y + b1);
            float2 hi = make_float2(a.z + b0, a.w + b1);
            if (relu) {
                lo.x = fmaxf(lo.x, 0.f); lo.y = fmaxf(lo.y, 0.f);
                hi.x = fmaxf(hi.x, 0.f); hi.y = fmaxf(hi.y, 0.f);
            }
            if (row < M)     *(float2*)(C + (size_t)row * N + col)       = lo;
            if (row + 8 < M) *(float2*)(C + (size_t)(row + 8) * N + col) = hi;
        }
    }
}

// ---------------- elementwise add: q = cur + pos ----------------
__global__ void ew_add(const float* __restrict__ x, const float* __restrict__ y,
                       float* __restrict__ out, int n)
{
    int i = blockIdx.x * blockDim.x + threadIdx.x;
    if (i < n) out[i] = x[i] + y[i];
}

// ---------------- reference points ----------------
__global__ void compute_ref(const float* __restrict__ vr, float* __restrict__ ref)
{
    int t = blockIdx.x * blockDim.x + threadIdx.x;
    if (t >= T_TOT) return;
    int b = t / S_TOT;
    int s = t - b * S_TOT;

    int lq, rem;
    if      (s >= 19950) { lq = 3; rem = s - 19950; }
    else if (s >= 19000) { lq = 2; rem = s - 19000; }
    else if (s >= 15200) { lq = 1; rem = s - 15200; }
    else                 { lq = 0; rem = s; }

    int H, W, st;
    level_consts(lq, H, W, st);
    int iy = rem / W;
    int ix = rem - iy * W;

    const float* v = vr + b * (NLEV * 2);
    float rx = (ix + 0.5f) / (v[lq * 2 + 0] * (float)W);
    float ry = (iy + 0.5f) / (v[lq * 2 + 1] * (float)H);

    #pragma unroll
    for (int l = 0; l < 4; l++) {
        ref[(size_t)t * 8 + l * 2 + 0] = rx * v[l * 2 + 0];
        ref[(size_t)t * 8 + l * 2 + 1] = ry * v[l * 2 + 1];
    }
}

// ---------------- softmax over 16 (per token,head) ----------------
__global__ void softmax16(float* __restrict__ attn, int n)
{
    int i = blockIdx.x * blockDim.x + threadIdx.x;
    if (i >= n) return;
    float* p = attn + (size_t)i * 16;
    float v[16], m = -1e30f;
    #pragma unroll
    for (int j = 0; j < 16; j++) { v[j] = p[j]; m = fmaxf(m, v[j]); }
    float s = 0.f;
    #pragma unroll
    for (int j = 0; j < 16; j++) { v[j] = expf(v[j] - m); s += v[j]; }
    float inv = 1.f / s;
    #pragma unroll
    for (int j = 0; j < 16; j++) p[j] = v[j] * inv;
}

// ---------------- MSDA bilinear sampling ----------------
__global__ __launch_bounds__(256) void msda_sample(
    const float* __restrict__ value, const float* __restrict__ off,
    const float* __restrict__ attn, const float* __restrict__ ref,
    float* __restrict__ acc)
{
    const int t = blockIdx.x;
    const int h = threadIdx.x >> 5;
    const int d = threadIdx.x & 31;
    const int b = (t >= S_TOT) ? 1 : 0;

    const float* vb = value + (size_t)b * S_TOT * DMODEL;
    const float* rp = ref  + (size_t)t * 8;
    const float* op = off  + (size_t)t * DMODEL + h * 32;
    const float* ap = attn + (size_t)t * 128 + h * 16;
    const int hd = h * HDIM + d;

    float a = 0.f;
    #pragma unroll
    for (int l = 0; l < 4; l++) {
        int Hl, Wl, st;
        level_consts(l, Hl, Wl, st);
        const float* vlev = vb + (size_t)st * DMODEL;
        float rx = rp[l * 2], ry = rp[l * 2 + 1];
        float invW = 1.f / (float)Wl, invH = 1.f / (float)Hl;
        #pragma unroll
        for (int p = 0; p < 4; p++) {
            float ox = op[l * 8 + p * 2], oy = op[l * 8 + p * 2 + 1];
            float w  = ap[l * 4 + p];
            float lx = rx + ox * invW;
            float ly = ry + oy * invH;
            float px = lx * (float)Wl - 0.5f;
            float py = ly * (float)Hl - 0.5f;
            float fx = floorf(px), fy = floorf(py);
            float dx = px - fx, dy = py - fy;
            int x0 = (int)fx, y0 = (int)fy;
            int x1 = x0 + 1, y1 = y0 + 1;
            bool vx0 = (x0 >= 0) & (x0 < Wl), vx1 = (x1 >= 0) & (x1 < Wl);
            bool vy0 = (y0 >= 0) & (y0 < Hl), vy1 = (y1 >= 0) & (y1 < Hl);
            int cx0 = min(max(x0, 0), Wl - 1), cx1 = min(max(x1, 0), Wl - 1);
            int cy0 = min(max(y0, 0), Hl - 1), cy1 = min(max(y1, 0), Hl - 1);
            float w00 = (vx0 && vy0) ? (1.f - dx) * (1.f - dy) : 0.f;
            float w10 = (vx1 && vy0) ? dx * (1.f - dy) : 0.f;
            float w01 = (vx0 && vy1) ? (1.f - dx) * dy : 0.f;
            float w11 = (vx1 && vy1) ? dx * dy : 0.f;
            float v00 = vlev[(size_t)(cy0 * Wl + cx0) * DMODEL + hd];
            float v10 = vlev[(size_t)(cy0 * Wl + cx1) * DMODEL + hd];
            float v01 = vlev[(size_t)(cy1 * Wl + cx0) * DMODEL + hd];
            float v11 = vlev[(size_t)(cy1 * Wl + cx1) * DMODEL + hd];
            float s = v00 * w00 + v10 * w10 + v01 * w01 + v11 * w11;
            a = fmaf(w, s, a);
        }
    }
    acc[(size_t)t * DMODEL + hd] = a;
}

// ---------------- residual add + layernorm (row = 256) ----------------
__global__ __launch_bounds__(256) void add_ln(
    const float* __restrict__ x, const float* __restrict__ r,
    const float* __restrict__ g, const float* __restrict__ bta,
    float* __restrict__ out)
{
    __shared__ float warpsum[8];
    __shared__ float bcast;
    const int row = blockIdx.x, tid = threadIdx.x;
    const int lane = tid & 31, wid = tid >> 5;

    float v = x[(size_t)row * 256 + tid] + r[(size_t)row * 256 + tid];

    float s = v;
    #pragma unroll
    for (int o = 16; o > 0; o >>= 1) s += __shfl_xor_sync(0xFFFFFFFFu, s, o);
    if (lane == 0) warpsum[wid] = s;
    __syncthreads();
    if (tid == 0) {
        float tt = 0.f;
        #pragma unroll
        for (int i = 0; i < 8; i++) tt += warpsum[i];
        bcast = tt * (1.f / 256.f);
    }
    __syncthreads();
    float mean = bcast;
    float dcen = v - mean;

    float s2 = dcen * dcen;
    #pragma unroll
    for (int o = 16; o > 0; o >>= 1) s2 += __shfl_xor_sync(0xFFFFFFFFu, s2, o);
    if (lane == 0) warpsum[wid] = s2;
    __syncthreads();
    if (tid == 0) {
        float tt = 0.f;
        #pragma unroll
        for (int i = 0; i < 8; i++) tt += warpsum[i];
        bcast = tt * (1.f / 256.f);
    }
    __syncthreads();
    float var = bcast;

    out[(size_t)row * 256 + tid] = dcen * rsqrtf(var + 1e-5f) * g[tid] + bta[tid];
}

// ---------------- host orchestration ----------------
static inline void run_gemm(const float* A, const float* W, const float* bias,
                            float* C, int M, int N, int K, int relu)
{
    dim3 grid((N + 127) / 128, (M + 127) / 128);
    gemm_tf32<<<grid, 256>>>(A, W, bias, C, M, N, K, relu);
}

extern "C" void kernel_launch(void* const* d_in, const int* in_sizes, int n_in,
                              void* d_out, int out_size)
{
    const float* src     = (const float*)d_in[0];
    const float* pos     = (const float*)d_in[1];
    const float* vratios = (const float*)d_in[2];
    const float* W_value = (const float*)d_in[3];
    const float* b_value = (const float*)d_in[4];
    const float* W_off   = (const float*)d_in[5];
    const float* b_off   = (const float*)d_in[6];
    const float* W_attn  = (const float*)d_in[7];
    const float* b_attn  = (const float*)d_in[8];
    const float* W_out   = (const float*)d_in[9];
    const float* b_out   = (const float*)d_in[10];
    const float* ln1g    = (const float*)d_in[11];
    const float* ln1b    = (const float*)d_in[12];
    const float* W_ff1   = (const float*)d_in[13];
    const float* b_ff1   = (const float*)d_in[14];
    const float* W_ff2   = (const float*)d_in[15];
    const float* b_ff2   = (const float*)d_in[16];
    const float* ln2g    = (const float*)d_in[17];
    const float* ln2b    = (const float*)d_in[18];

    float *pval, *pq, *poff, *pattn, *pacc, *pa, *pff, *pcur, *pref;
    cudaGetSymbolAddress((void**)&pval,  g_value);
    cudaGetSymbolAddress((void**)&pq,    g_q);
    cudaGetSymbolAddress((void**)&poff,  g_off);
    cudaGetSymbolAddress((void**)&pattn, g_attn);
    cudaGetSymbolAddress((void**)&pacc,  g_acc);
    cudaGetSymbolAddress((void**)&pa,    g_a);
    cudaGetSymbolAddress((void**)&pff,   g_ff);
    cudaGetSymbolAddress((void**)&pcur,  g_cur);
    cudaGetSymbolAddress((void**)&pref,  g_ref);

    const int nElem = T_TOT * DMODEL;
    const int M = T_TOT;

    compute_ref<<<(T_TOT + 255) / 256, 256>>>(vratios, pref);

    const float* cur = src;
    for (int i = 0; i < NLAYERS; i++) {
        const float* Wv  = W_value + (size_t)i * DMODEL * DMODEL;
        const float* bv  = b_value + (size_t)i * DMODEL;
        const float* Wof = W_off   + (size_t)i * DMODEL * DMODEL;
        const float* bof = b_off   + (size_t)i * DMODEL;
        const float* Wat = W_attn  + (size_t)i * DMODEL * 128;
        const float* bat = b_attn  + (size_t)i * 128;
        const float* Wo  = W_out   + (size_t)i * DMODEL * DMODEL;
        const float* bo  = b_out   + (size_t)i * DMODEL;
        const float* Wf1 = W_ff1   + (size_t)i * DMODEL * DFF;
        const float* bf1 = b_ff1   + (size_t)i * DFF;
        const float* Wf2 = W_ff2   + (size_t)i * DFF * DMODEL;
        const float* bf2 = b_ff2   + (size_t)i * DMODEL;

        // value projection
        run_gemm(cur, Wv, bv, pval, M, DMODEL, DMODEL, 0);
        // q = cur + pos
        ew_add<<<(nElem + 255) / 256, 256>>>(cur, pos, pq, nElem);
        // offsets / attention logits
        run_gemm(pq, Wof, bof, poff, M, DMODEL, DMODEL, 0);
        run_gemm(pq, Wat, bat, pattn, M, 128, DMODEL, 0);
        softmax16<<<(T_TOT * NHEAD + 255) / 256, 256>>>(pattn, T_TOT * NHEAD);
        // deformable sampling
        msda_sample<<<T_TOT, 256>>>(pval, poff, pattn, pref, pacc);
        // output projection + residual LN
        run_gemm(pacc, Wo, bo, pa, M, DMODEL, DMODEL, 0);
        add_ln<<<T_TOT, 256>>>(cur, pa, ln1g + (size_t)i * DMODEL,
                               ln1b + (size_t)i * DMODEL, pcur);
        // FFN
        run_gemm(pcur, Wf1, bf1, pff, M, DFF, DMODEL, 1);
        run_gemm(pff, Wf2, bf2, pa, M, DMODEL, DFF, 0);
        float* dst = (i == NLAYERS - 1) ? (float*)d_out : pcur;
        add_ln<<<T_TOT, 256>>>(pcur, pa, ln2g + (size_t)i * DMODEL,
                               ln2b + (size_t)i * DMODEL, dst);
        cur = pcur;
    }
}

// round 14
// speedup vs baseline: 1.9065x; 1.2922x over previous
#include <cuda_runtime.h>
#include <math.h>
#include <stdint.h>

// ---------------- problem constants ----------------
#define S_TOT   20197
#define BATCH   2
#define T_TOT   40394          // BATCH * S_TOT
#define DMODEL  256
#define NHEAD   8
#define HDIM    32
#define NLEV    4
#define NPNT    4
#define DFF     1024
#define NLAYERS 6

// level geometry
__device__ __forceinline__ void level_consts(int l, int& H, int& W, int& start) {
    const int Hs[4] = {100, 50, 25, 13};
    const int Ws[4] = {152, 76, 38, 19};
    const int St[4] = {0, 15200, 19000, 19950};
    H = Hs[l]; W = Ws[l]; start = St[l];
}

// ---------------- scratch (static device memory, no allocs) ----------------
__device__ float g_value[(size_t)T_TOT * DMODEL];
__device__ float g_q    [(size_t)T_TOT * DMODEL];
__device__ float g_off  [(size_t)T_TOT * DMODEL];
__device__ float g_attn [(size_t)T_TOT * (NHEAD * NLEV * NPNT)];
__device__ float g_acc  [(size_t)T_TOT * DMODEL];
__device__ float g_a    [(size_t)T_TOT * DMODEL];
__device__ float g_ff   [(size_t)T_TOT * DFF];
__device__ float g_cur  [(size_t)T_TOT * DMODEL];
__device__ float g_ref  [(size_t)T_TOT * NLEV * 2];

// ================= helpers ==========================
__device__ __forceinline__ uint32_t smem_u32(const void* p) {
    uint32_t a;
    asm("{ .reg .u64 t; cvta.to.shared.u64 t, %1; cvt.u32.u64 %0, t; }"
        : "=r"(a) : "l"(p));
    return a;
}

__device__ __forceinline__ void mma_16n8k8(float* d,
    uint32_t a0, uint32_t a1, uint32_t a2, uint32_t a3,
    uint32_t b0, uint32_t b1)
{
    asm volatile(
        "mma.sync.aligned.m16n8k8.row.col.f32.tf32.tf32.f32 "
        "{%0,%1,%2,%3}, {%4,%5,%6,%7}, {%8,%9}, {%0,%1,%2,%3};"
        : "+f"(d[0]), "+f"(d[1]), "+f"(d[2]), "+f"(d[3])
        : "r"(a0), "r"(a1), "r"(a2), "r"(a3), "r"(b0), "r"(b1));
}

#define CP_ASYNC_16(dst, src, sz) \
    asm volatile("cp.async.cg.shared.global [%0], [%1], 16, %2;" \
        :: "r"(dst), "l"(src), "r"(sz) : "memory")
#define CP_COMMIT() asm volatile("cp.async.commit_group;" ::: "memory")
#define CP_WAIT(n)  asm volatile("cp.async.wait_group %0;" :: "n"(n) : "memory")

// ================= cp.async pipelined mma.sync tf32 GEMM ===================
// C[M,N] = A[M,K] @ W[K,N] + bias (optional relu).
// BM=BN=128, BK=16, 256 threads = 8 warps (2 x 4), warp tile 64x32.
// 3-stage cp.async pipeline; fp32 bits fed to tf32 MMA (HW truncation).
// SMEM per stage: A[128][20] floats (pad 20), B[16][132] floats (pad 132);
// both pads make all fragment LDS.32 bank-conflict-free.
#define GSTAGES   3
#define A_STRIDE  20
#define B_STRIDE  132
#define STAGE_FLTS (128 * A_STRIDE + 16 * B_STRIDE)   // 4672
#define GEMM_SMEM (GSTAGES * STAGE_FLTS * 4)          // 56064 bytes

__global__ __launch_bounds__(256) void gemm_tf32(
    const float* __restrict__ A, const float* __restrict__ W,
    const float* __restrict__ bias, float* __restrict__ C,
    int M, int N, int K, int relu)
{
    extern __shared__ float sm[];
    const int tid   = threadIdx.x;
    const int lane  = tid & 31;
    const int wid   = tid >> 5;
    const int warpM = wid & 1;          // 0..1 -> M offset 0/64
    const int warpN = wid >> 1;         // 0..3 -> N offset 0/32/64/96
    const int m0 = blockIdx.y * 128;
    const int n0 = blockIdx.x * 128;
    const int qr = lane >> 2;           // 0..7
    const int qc = lane & 3;            // 0..3

    const uint32_t smBase = smem_u32(sm);

    // cp.async indices: 256 threads move A(128x16) and B(16x128), 2 chunks each
    const int aRow0 = tid >> 2;          // 0..63 (+64)
    const int aC4   = (tid & 3) << 2;    // 0,4,8,12
    const int bK0   = tid >> 5;          // 0..7 (+8)
    const int bN4   = (tid & 31) << 2;   // 0..124

    float acc[4][4][4];
    #pragma unroll
    for (int i = 0; i < 4; i++)
        #pragma unroll
        for (int j = 0; j < 4; j++)
            #pragma unroll
            for (int k = 0; k < 4; k++) acc[i][j][k] = 0.f;

    const int nChunks = K >> 4;

    auto issue = [&](int c) {
        const int st = c % GSTAGES;
        const int k0 = c << 4;
        const uint32_t aBase = smBase + (uint32_t)(st * STAGE_FLTS) * 4u;
        const uint32_t bBase = aBase + 128u * A_STRIDE * 4u;
        #pragma unroll
        for (int i = 0; i < 2; i++) {
            int row = aRow0 + i * 64;
            int gr  = m0 + row;
            int sz  = (gr < M) ? 16 : 0;
            int grc = gr < M ? gr : (M - 1);
            const float* src = A + (size_t)grc * K + k0 + aC4;
            uint32_t dst = aBase + (uint32_t)(row * A_STRIDE + aC4) * 4u;
            CP_ASYNC_16(dst, src, sz);
        }
        #pragma unroll
        for (int i = 0; i < 2; i++) {
            int k = bK0 + i * 8;
            const float* src = W + (size_t)(k0 + k) * N + n0 + bN4;
            uint32_t dst = bBase + (uint32_t)(k * B_STRIDE + bN4) * 4u;
            CP_ASYNC_16(dst, src, 16);
        }
        CP_COMMIT();
    };

    issue(0);
    if (nChunks > 1) issue(1);

    for (int c = 0; c < nChunks; c++) {
        if (c + 1 < nChunks) { CP_WAIT(1); } else { CP_WAIT(0); }
        __syncthreads();
        if (c + 2 < nChunks) issue(c + 2);

        const int st = c % GSTAGES;
        const float* As_ = sm + st * STAGE_FLTS;
        const float* Bs_ = As_ + 128 * A_STRIDE;

        #pragma unroll
        for (int s = 0; s < 2; s++) {
            const int ka  = qc + s * 8;
            const int ka2 = ka + 4;
            uint32_t af[4][4];
            #pragma unroll
            for (int mt = 0; mt < 4; mt++) {
                int r = warpM * 64 + mt * 16 + qr;
                af[mt][0] = __float_as_uint(As_[r * A_STRIDE + ka]);
                af[mt][1] = __float_as_uint(As_[(r + 8) * A_STRIDE + ka]);
                af[mt][2] = __float_as_uint(As_[r * A_STRIDE + ka2]);
                af[mt][3] = __float_as_uint(As_[(r + 8) * A_STRIDE + ka2]);
            }
            uint32_t bfr[4][2];
            #pragma unroll
            for (int nt = 0; nt < 4; nt++) {
                int n = warpN * 32 + nt * 8 + qr;
                bfr[nt][0] = __float_as_uint(Bs_[ka  * B_STRIDE + n]);
                bfr[nt][1] = __float_as_uint(Bs_[ka2 * B_STRIDE + n]);
            }
            #pragma unroll
            for (int mt = 0; mt < 4; mt++)
                #pragma unroll
                for (int nt = 0; nt < 4; nt++)
                    mma_16n8k8(acc[mt][nt],
                               af[mt][0], af[mt][1], af[mt][2], af[mt][3],
                               bfr[nt][0], bfr[nt][1]);
        }
    }

    // ---- epilogue: bias + optional relu ----
    #pragma unroll
    for (int nt = 0; nt < 4; nt++) {
        int col = n0 + warpN * 32 + nt * 8 + qc * 2;
        float b0 = bias[col], b1 = bias[col + 1];
        #pragma unroll
        for (int mt = 0; mt < 4; mt++) {
            int row = m0 + warpM * 64 + mt * 16 + qr;
            float2 lo = make_float2(acc[mt][nt][0] + b0, acc[mt][nt][1] + b1);
            float2 hi = make_float2(acc[mt][nt][2] + b0, acc[mt][nt][3] + b1);
            if (relu) {
                lo.x = fmaxf(lo.x, 0.f); lo.y = fmaxf(lo.y, 0.f);
                hi.x = fmaxf(hi.x, 0.f); hi.y = fmaxf(hi.y, 0.f);
            }
            if (row < M)     *(float2*)(C + (size_t)row * N + col)       = lo;
            if (row + 8 < M) *(float2*)(C + (size_t)(row + 8) * N + col) = hi;
        }
    }
}

// ---------------- elementwise add: q = cur + pos ----------------
__global__ void ew_add(const float* __restrict__ x, const float* __restrict__ y,
                       float* __restrict__ out, int n)
{
    int i = blockIdx.x * blockDim.x + threadIdx.x;
    if (i < n) out[i] = x[i] + y[i];
}

// ---------------- reference points ----------------
__global__ void compute_ref(const float* __restrict__ vr, float* __restrict__ ref)
{
    int t = blockIdx.x * blockDim.x + threadIdx.x;
    if (t >= T_TOT) return;
    int b = t / S_TOT;
    int s = t - b * S_TOT;

    int lq, rem;
    if      (s >= 19950) { lq = 3; rem = s - 19950; }
    else if (s >= 19000) { lq = 2; rem = s - 19000; }
    else if (s >= 15200) { lq = 1; rem = s - 15200; }
    else                 { lq = 0; rem = s; }

    int H, W, st;
    level_consts(lq, H, W, st);
    int iy = rem / W;
    int ix = rem - iy * W;

    const float* v = vr + b * (NLEV * 2);
    float rx = (ix + 0.5f) / (v[lq * 2 + 0] * (float)W);
    float ry = (iy + 0.5f) / (v[lq * 2 + 1] * (float)H);

    #pragma unroll
    for (int l = 0; l < 4; l++) {
        ref[(size_t)t * 8 + l * 2 + 0] = rx * v[l * 2 + 0];
        ref[(size_t)t * 8 + l * 2 + 1] = ry * v[l * 2 + 1];
    }
}

// ---------------- MSDA bilinear sampling (softmax fused) ----------------
// one block per token; warp = head; lane = head-dim
__global__ __launch_bounds__(256) void msda_sample(
    const float* __restrict__ value, const float* __restrict__ off,
    const float* __restrict__ logits, const float* __restrict__ ref,
    float* __restrict__ acc)
{
    __shared__ float sw[NHEAD][16];
    const int t = blockIdx.x;
    const int h = threadIdx.x >> 5;
    const int d = threadIdx.x & 31;
    const int b = (t >= S_TOT) ? 1 : 0;

    // ---- warp softmax over the 16 attention logits of this (token, head) ----
    {
        const float* lp = logits + (size_t)t * 128 + h * 16;
        float lg = (d < 16) ? lp[d] : -1e30f;
        float mx = lg;
        #pragma unroll
        for (int o = 8; o > 0; o >>= 1) mx = fmaxf(mx, __shfl_xor_sync(0xFFFFFFFFu, mx, o));
        float e = (d < 16) ? expf(lg - mx) : 0.f;
        float s = e;
        #pragma unroll
        for (int o = 8; o > 0; o >>= 1) s += __shfl_xor_sync(0xFFFFFFFFu, s, o);
        if (d < 16) sw[h][d] = e / s;
        __syncwarp();
    }

    const float* vb = value + (size_t)b * S_TOT * DMODEL;
    const float* rp = ref  + (size_t)t * 8;
    const float* op = off  + (size_t)t * DMODEL + h * 32;
    const int hd = h * HDIM + d;

    float a = 0.f;
    #pragma unroll
    for (int l = 0; l < 4; l++) {
        int Hl, Wl, st;
        level_consts(l, Hl, Wl, st);
        const float* vlev = vb + (size_t)st * DMODEL;
        float rx = rp[l * 2], ry = rp[l * 2 + 1];
        float invW = 1.f / (float)Wl, invH = 1.f / (float)Hl;
        #pragma unroll
        for (int p = 0; p < 4; p++) {
            float ox = op[l * 8 + p * 2], oy = op[l * 8 + p * 2 + 1];
            float w  = sw[h][l * 4 + p];
            float lx = rx + ox * invW;
            float ly = ry + oy * invH;
            float px = lx * (float)Wl - 0.5f;
            float py = ly * (float)Hl - 0.5f;
            float fx = floorf(px), fy = floorf(py);
            float dx = px - fx, dy = py - fy;
            int x0 = (int)fx, y0 = (int)fy;
            int x1 = x0 + 1, y1 = y0 + 1;
            bool vx0 = (x0 >= 0) & (x0 < Wl), vx1 = (x1 >= 0) & (x1 < Wl);
            bool vy0 = (y0 >= 0) & (y0 < Hl), vy1 = (y1 >= 0) & (y1 < Hl);
            int cx0 = min(max(x0, 0), Wl - 1), cx1 = min(max(x1, 0), Wl - 1);
            int cy0 = min(max(y0, 0), Hl - 1), cy1 = min(max(y1, 0), Hl - 1);
            float w00 = (vx0 && vy0) ? (1.f - dx) * (1.f - dy) : 0.f;
            float w10 = (vx1 && vy0) ? dx * (1.f - dy) : 0.f;
            float w01 = (vx0 && vy1) ? (1.f - dx) * dy : 0.f;
            float w11 = (vx1 && vy1) ? dx * dy : 0.f;
            float v00 = vlev[(size_t)(cy0 * Wl + cx0) * DMODEL + hd];
            float v10 = vlev[(size_t)(cy0 * Wl + cx1) * DMODEL + hd];
            float v01 = vlev[(size_t)(cy1 * Wl + cx0) * DMODEL + hd];
            float v11 = vlev[(size_t)(cy1 * Wl + cx1) * DMODEL + hd];
            float s = v00 * w00 + v10 * w10 + v01 * w01 + v11 * w11;
            a = fmaf(w, s, a);
        }
    }
    acc[(size_t)t * DMODEL + hd] = a;
}

// ---------------- residual add + layernorm (row = 256) ----------------
__global__ __launch_bounds__(256) void add_ln(
    const float* __restrict__ x, const float* __restrict__ r,
    const float* __restrict__ g, const float* __restrict__ bta,
    float* __restrict__ out)
{
    __shared__ float warpsum[8];
    __shared__ float bcast;
    const int row = blockIdx.x, tid = threadIdx.x;
    const int lane = tid & 31, wid = tid >> 5;

    float v = x[(size_t)row * 256 + tid] + r[(size_t)row * 256 + tid];

    float s = v;
    #pragma unroll
    for (int o = 16; o > 0; o >>= 1) s += __shfl_xor_sync(0xFFFFFFFFu, s, o);
    if (lane == 0) warpsum[wid] = s;
    __syncthreads();
    if (tid == 0) {
        float tt = 0.f;
        #pragma unroll
        for (int i = 0; i < 8; i++) tt += warpsum[i];
        bcast = tt * (1.f / 256.f);
    }
    __syncthreads();
    float mean = bcast;
    float dcen = v - mean;

    float s2 = dcen * dcen;
    #pragma unroll
    for (int o = 16; o > 0; o >>= 1) s2 += __shfl_xor_sync(0xFFFFFFFFu, s2, o);
    if (lane == 0) warpsum[wid] = s2;
    __syncthreads();
    if (tid == 0) {
        float tt = 0.f;
        #pragma unroll
        for (int i = 0; i < 8; i++) tt += warpsum[i];
        bcast = tt * (1.f / 256.f);
    }
    __syncthreads();
    float var = bcast;

    out[(size_t)row * 256 + tid] = dcen * rsqrtf(var + 1e-5f) * g[tid] + bta[tid];
}

// ---------------- host orchestration ----------------
static inline void run_gemm(const float* A, const float* W, const float* bias,
                            float* C, int M, int N, int K, int relu)
{
    dim3 grid(N / 128, (M + 127) / 128);
    gemm_tf32<<<grid, 256, GEMM_SMEM>>>(A, W, bias, C, M, N, K, relu);
}

extern "C" void kernel_launch(void* const* d_in, const int* in_sizes, int n_in,
                              void* d_out, int out_size)
{
    const float* src     = (const float*)d_in[0];
    const float* pos     = (const float*)d_in[1];
    const float* vratios = (const float*)d_in[2];
    const float* W_value = (const float*)d_in[3];
    const float* b_value = (const float*)d_in[4];
    const float* W_off   = (const float*)d_in[5];
    const float* b_off   = (const float*)d_in[6];
    const float* W_attn  = (const float*)d_in[7];
    const float* b_attn  = (const float*)d_in[8];
    const float* W_out   = (const float*)d_in[9];
    const float* b_out   = (const float*)d_in[10];
    const float* ln1g    = (const float*)d_in[11];
    const float* ln1b    = (const float*)d_in[12];
    const float* W_ff1   = (const float*)d_in[13];
    const float* b_ff1   = (const float*)d_in[14];
    const float* W_ff2   = (const float*)d_in[15];
    const float* b_ff2   = (const float*)d_in[16];
    const float* ln2g    = (const float*)d_in[17];
    const float* ln2b    = (const float*)d_in[18];

    cudaFuncSetAttribute(gemm_tf32, cudaFuncAttributeMaxDynamicSharedMemorySize,
                         GEMM_SMEM);

    float *pval, *pq, *poff, *pattn, *pacc, *pa, *pff, *pcur, *pref;
    cudaGetSymbolAddress((void**)&pval,  g_value);
    cudaGetSymbolAddress((void**)&pq,    g_q);
    cudaGetSymbolAddress((void**)&poff,  g_off);
    cudaGetSymbolAddress((void**)&pattn, g_attn);
    cudaGetSymbolAddress((void**)&pacc,  g_acc);
    cudaGetSymbolAddress((void**)&pa,    g_a);
    cudaGetSymbolAddress((void**)&pff,   g_ff);
    cudaGetSymbolAddress((void**)&pcur,  g_cur);
    cudaGetSymbolAddress((void**)&pref,  g_ref);

    const int nElem = T_TOT * DMODEL;
    const int M = T_TOT;

    compute_ref<<<(T_TOT + 255) / 256, 256>>>(vratios, pref);

    const float* cur = src;
    for (int i = 0; i < NLAYERS; i++) {
        const float* Wv  = W_value + (size_t)i * DMODEL * DMODEL;
        const float* bv  = b_value + (size_t)i * DMODEL;
        const float* Wof = W_off   + (size_t)i * DMODEL * DMODEL;
        const float* bof = b_off   + (size_t)i * DMODEL;
        const float* Wat = W_attn  + (size_t)i * DMODEL * 128;
        const float* bat = b_attn  + (size_t)i * 128;
        const float* Wo  = W_out   + (size_t)i * DMODEL * DMODEL;
        const float* bo  = b_out   + (size_t)i * DMODEL;
        const float* Wf1 = W_ff1   + (size_t)i * DMODEL * DFF;
        const float* bf1 = b_ff1   + (size_t)i * DFF;
        const float* Wf2 = W_ff2   + (size_t)i * DFF * DMODEL;
        const float* bf2 = b_ff2   + (size_t)i * DMODEL;

        // value projection
        run_gemm(cur, Wv, bv, pval, M, DMODEL, DMODEL, 0);
        // q = cur + pos
        ew_add<<<(nElem + 255) / 256, 256>>>(cur, pos, pq, nElem);
        // offsets / attention logits
        run_gemm(pq, Wof, bof, poff, M, DMODEL, DMODEL, 0);
        run_gemm(pq, Wat, bat, pattn, M, 128, DMODEL, 0);
        // deformable sampling (softmax fused)
        msda_sample<<<T_TOT, 256>>>(pval, poff, pattn, pref, pacc);
        // output projection + residual LN
        run_gemm(pacc, Wo, bo, pa, M, DMODEL, DMODEL, 0);
        add_ln<<<T_TOT, 256>>>(cur, pa, ln1g + (size_t)i * DMODEL,
                               ln1b + (size_t)i * DMODEL, pcur);
        // FFN
        run_gemm(pcur, Wf1, bf1, pff, M, DFF, DMODEL, 1);
        run_gemm(pff, Wf2, bf2, pa, M, DMODEL, DFF, 0);
        float* dst = (i == NLAYERS - 1) ? (float*)d_out : pcur;
        add_ln<<<T_TOT, 256>>>(pcur, pa, ln2g + (size_t)i * DMODEL,
                               ln2b + (size_t)i * DMODEL, dst);
        cur = pcur;
    }
}